// round 2
// baseline (speedup 1.0000x reference)
#include <cuda_runtime.h>
#include <cstdint>

#define N_NODES 100000
#define D 128
#define N_EDGES 1000000

// Scratch (no allocation allowed -> __device__ globals). 16B-aligned for
// float4 / red.v4 access.
__device__ alignas(16) float g_agg[(size_t)N_NODES * D];   // aggregation accumulator
__device__ alignas(16) float g_h1 [(size_t)N_NODES * D];   // layer-1 output (post-ReLU)
__device__ alignas(16) float g_cnt[N_NODES];
__device__ alignas(16) float g_inv[N_NODES];

// ---------------------------------------------------------------------------
// Zero a float buffer (count4 = number of float4 elements)
// ---------------------------------------------------------------------------
__global__ void zero_kernel(float4* p, int count4) {
    int i = blockIdx.x * blockDim.x + threadIdx.x;
    int stride = gridDim.x * blockDim.x;
    float4 z = make_float4(0.f, 0.f, 0.f, 0.f);
    for (; i < count4; i += stride) p[i] = z;
}

// ---------------------------------------------------------------------------
// Edge counts per destination (edge_index is int32: [2, E] row-major)
// ---------------------------------------------------------------------------
__global__ void count_kernel(const int* __restrict__ ei) {
    int i = blockIdx.x * blockDim.x + threadIdx.x;
    int stride = gridDim.x * blockDim.x;
    for (; i < N_EDGES; i += stride) {
        int d = ei[N_EDGES + i];
        d = min(max(d, 0), N_NODES - 1);
        atomicAdd(&g_cnt[d], 1.0f);
    }
}

__global__ void inv_kernel() {
    int i = blockIdx.x * blockDim.x + threadIdx.x;
    if (i < N_NODES) g_inv[i] = 1.0f / fmaxf(g_cnt[i], 1.0f);
}

// ---------------------------------------------------------------------------
// Scatter: one warp per edge; lane l handles float4 l of the 128-float row.
// Vector reduction (red.global.add.v4.f32) -> 1 instr per 16B.
// ---------------------------------------------------------------------------
__global__ void scatter_kernel(const int* __restrict__ ei,
                               const float* __restrict__ x) {
    int gt = blockIdx.x * blockDim.x + threadIdx.x;
    int lane = gt & 31;
    int warp = gt >> 5;
    int nwarps = (gridDim.x * blockDim.x) >> 5;
    for (int e = warp; e < N_EDGES; e += nwarps) {
        int s = ei[e];                 // broadcast load (all lanes same addr)
        int d = ei[N_EDGES + e];
        s = min(max(s, 0), N_NODES - 1);
        d = min(max(d, 0), N_NODES - 1);
        const float4* srcp = (const float4*)(x + (size_t)s * D);
        float4 v = srcp[lane];
        float* dst = g_agg + (size_t)d * D + lane * 4;
        asm volatile("red.global.add.v4.f32 [%0], {%1,%2,%3,%4};"
                     :: "l"(dst), "f"(v.x), "f"(v.y), "f"(v.z), "f"(v.w)
                     : "memory");
    }
}

// ---------------------------------------------------------------------------
// Fused SAGE GEMM:
//   out[n,:] = act( (agg[n,:]*inv[n]) @ Wl + x[n,:] @ Wr + b )
// Treated as one GEMM: A' = [agg*inv | x]  (K=256), W' = [Wl ; Wr].
// Block: 256 threads, tile M=128 x N=128, K chunked by 64.
// Weights persistent in SMEM (128 KB); A-tile 128x65 padded (33.3 KB).
// Each thread: 8x8 register outer product.
// ---------------------------------------------------------------------------
#define GEMM_SMEM_BYTES ((256 * 128 + 128 * 65) * 4)

__global__ void __launch_bounds__(256, 1)
sage_gemm(const float* __restrict__ x,
          const float* __restrict__ wl,
          const float* __restrict__ wr,
          const float* __restrict__ bias,
          float* __restrict__ out,
          int do_relu) {
    extern __shared__ float sm[];
    float* wS = sm;                 // [256][128], k-major
    float* aS = sm + 256 * 128;     // [128][65]  (padded)

    const int tid = threadIdx.x;
    const int tx = tid & 15;        // n-group: cols tx*8 .. tx*8+7
    const int ty = tid >> 4;        // m-group: rows ty*8 .. ty*8+7
    const int m_base = blockIdx.x * 128;

    // Stage weights once: wS[k][j], k<128 -> Wl, else Wr. 8192 float4 slots.
    {
        const float4* wl4 = (const float4*)wl;
        const float4* wr4 = (const float4*)wr;
        float4* wS4 = (float4*)wS;
        for (int i = tid; i < 8192; i += 256) {
            int k = i >> 5;
            int jq = i & 31;
            wS4[i] = (k < 128) ? wl4[k * 32 + jq] : wr4[(k - 128) * 32 + jq];
        }
    }

    float acc[8][8];
#pragma unroll
    for (int i = 0; i < 8; i++)
#pragma unroll
        for (int j = 0; j < 8; j++) acc[i][j] = 0.f;

    __syncthreads();

    for (int chunk = 0; chunk < 4; chunk++) {
        // Stage A-tile: aS[m][kk] = A'[m_base+m][chunk*64+kk]
        // 2048 float4 slots: slot -> m = slot>>4, kq = slot&15
        for (int i = tid; i < 2048; i += 256) {
            int m = i >> 4;
            int kq = i & 15;
            int gm = m_base + m;
            float4 v = make_float4(0.f, 0.f, 0.f, 0.f);
            if (gm < N_NODES) {
                int kg = chunk * 64 + kq * 4;
                if (kg < 128) {
                    v = *(const float4*)(g_agg + (size_t)gm * D + kg);
                    float s = g_inv[gm];
                    v.x *= s; v.y *= s; v.z *= s; v.w *= s;
                } else {
                    v = *(const float4*)(x + (size_t)gm * D + (kg - 128));
                }
            }
            float* p = &aS[m * 65 + kq * 4];
            p[0] = v.x; p[1] = v.y; p[2] = v.z; p[3] = v.w;
        }
        __syncthreads();

        const float* wbase = wS + (chunk * 64) * 128 + tx * 8;
#pragma unroll 8
        for (int kk = 0; kk < 64; kk++) {
            float4 w0 = *(const float4*)(wbase + kk * 128);
            float4 w1 = *(const float4*)(wbase + kk * 128 + 4);
            float w[8] = {w0.x, w0.y, w0.z, w0.w, w1.x, w1.y, w1.z, w1.w};
            float a[8];
#pragma unroll
            for (int i = 0; i < 8; i++) a[i] = aS[(ty * 8 + i) * 65 + kk];
#pragma unroll
            for (int i = 0; i < 8; i++) {
                float av = a[i];
#pragma unroll
                for (int j = 0; j < 8; j++) acc[i][j] += av * w[j];
            }
        }
        __syncthreads();
    }

    // Epilogue: bias (+ReLU), store
    const int j0 = tx * 8;
    float4 bv0 = *(const float4*)(bias + j0);
    float4 bv1 = *(const float4*)(bias + j0 + 4);
    float bb[8] = {bv0.x, bv0.y, bv0.z, bv0.w, bv1.x, bv1.y, bv1.z, bv1.w};
#pragma unroll
    for (int i = 0; i < 8; i++) {
        int gm = m_base + ty * 8 + i;
        if (gm >= N_NODES) continue;
        float r[8];
#pragma unroll
        for (int j = 0; j < 8; j++) {
            float v = acc[i][j] + bb[j];
            r[j] = do_relu ? fmaxf(v, 0.f) : v;
        }
        float* op = out + (size_t)gm * D + j0;
        *(float4*)(op)     = make_float4(r[0], r[1], r[2], r[3]);
        *(float4*)(op + 4) = make_float4(r[4], r[5], r[6], r[7]);
    }
}

// ---------------------------------------------------------------------------
// Launcher
// ---------------------------------------------------------------------------
extern "C" void kernel_launch(void* const* d_in, const int* in_sizes, int n_in,
                              void* d_out, int out_size) {
    const int* edge_index = (const int*)d_in[0];   // int32 (JAX default int)
    const float* node_emb = (const float*)d_in[1];
    const float* w1_l = (const float*)d_in[2];
    const float* b1_l = (const float*)d_in[3];
    const float* w1_r = (const float*)d_in[4];
    const float* w2_l = (const float*)d_in[5];
    const float* b2_l = (const float*)d_in[6];
    const float* w2_r = (const float*)d_in[7];
    float* out = (float*)d_out;

    static bool attr_set = false;
    if (!attr_set) {
        cudaFuncSetAttribute(sage_gemm, cudaFuncAttributeMaxDynamicSharedMemorySize,
                             GEMM_SMEM_BYTES);
        attr_set = true;
    }

    float* agg_p;  cudaGetSymbolAddress((void**)&agg_p, g_agg);
    float* cnt_p;  cudaGetSymbolAddress((void**)&cnt_p, g_cnt);
    float* h1_p;   cudaGetSymbolAddress((void**)&h1_p, g_h1);

    const int zb = 2048, zt = 256;
    const int agg4 = N_NODES * D / 4;

    // --- counts (once) ---
    zero_kernel<<<64, 256>>>((float4*)cnt_p, N_NODES / 4);
    count_kernel<<<1024, 256>>>(edge_index);
    inv_kernel<<<(N_NODES + 255) / 256, 256>>>();

    const int gemm_blocks = (N_NODES + 127) / 128;

    // --- layer 1 ---
    zero_kernel<<<zb, zt>>>((float4*)agg_p, agg4);
    scatter_kernel<<<2048, 256>>>(edge_index, node_emb);
    sage_gemm<<<gemm_blocks, 256, GEMM_SMEM_BYTES>>>(node_emb, w1_l, w1_r, b1_l,
                                                     h1_p, 1);

    // --- layer 2 ---
    zero_kernel<<<zb, zt>>>((float4*)agg_p, agg4);
    scatter_kernel<<<2048, 256>>>(edge_index, h1_p);
    sage_gemm<<<gemm_blocks, 256, GEMM_SMEM_BYTES>>>(h1_p, w2_l, w2_r, b2_l,
                                                     out, 0);

    (void)in_sizes; (void)n_in; (void)out_size;
}

// round 4
// speedup vs baseline: 1.6567x; 1.6567x over previous
#include <cuda_runtime.h>
#include <cstdint>

#define N_NODES 100000
#define D 128
#define N_EDGES 1000000
#define M_TILE 128
#define NUM_TILES ((N_NODES + M_TILE - 1) / M_TILE)   // 782

// Scratch (no allocation allowed -> __device__ globals)
__device__ alignas(16) float g_agg[(size_t)N_NODES * D];
__device__ alignas(16) float g_h1 [(size_t)N_NODES * D];
__device__ alignas(16) float g_cnt[N_NODES];
__device__ alignas(16) float g_inv[N_NODES];

// ---------------------------------------------------------------------------
// Simple kernels
// ---------------------------------------------------------------------------
__global__ void zero_kernel(float4* p, int count4) {
    int i = blockIdx.x * blockDim.x + threadIdx.x;
    int stride = gridDim.x * blockDim.x;
    float4 z = make_float4(0.f, 0.f, 0.f, 0.f);
    for (; i < count4; i += stride) p[i] = z;
}

__global__ void inv_kernel() {
    int i = blockIdx.x * blockDim.x + threadIdx.x;
    if (i < N_NODES) g_inv[i] = 1.0f / fmaxf(g_cnt[i], 1.0f);
}

// Scatter: one warp per edge; lane l handles float4 l of the 128-float row.
// do_count: lane 0 also bumps the destination degree counter (layer 1 only).
__global__ void scatter_kernel(const int* __restrict__ ei,
                               const float* __restrict__ x,
                               int do_count) {
    int gt = blockIdx.x * blockDim.x + threadIdx.x;
    int lane = gt & 31;
    int warp = gt >> 5;
    int nwarps = (gridDim.x * blockDim.x) >> 5;
    for (int e = warp; e < N_EDGES; e += nwarps) {
        int s = ei[e];
        int d = ei[N_EDGES + e];
        s = min(max(s, 0), N_NODES - 1);
        d = min(max(d, 0), N_NODES - 1);
        if (do_count && lane == 0) atomicAdd(&g_cnt[d], 1.0f);
        const float4* srcp = (const float4*)(x + (size_t)s * D);
        float4 v = srcp[lane];
        float* dst = g_agg + (size_t)d * D + lane * 4;
        asm volatile("red.global.add.v4.f32 [%0], {%1,%2,%3,%4};"
                     :: "l"(dst), "f"(v.x), "f"(v.y), "f"(v.z), "f"(v.w)
                     : "memory");
    }
}

// ---------------------------------------------------------------------------
// Tensor-core fused SAGE GEMM via mma.sync tf32 (m16n8k8) — sm_100-legal.
//   out[m,:] = act( (agg[m,:]*inv[m]) @ Wl + x[m,:] @ Wr + b )
// One GEMM: A' = [agg*inv | x] (K=256), B = W'^T staged [K=256][N=128].
// Block: 512 threads = 16 warps in a 4x4 grid; warp tile 32(m) x 32(n).
// SMEM strides chosen for conflict-free mma-fragment LDS:
//   wS stride 136 words: bank(k,n) = 8k+n  (k=lane%4, n=lane/4) bijective
//   aS stride  68 words: bank(m,k) = 4m+k  (m=lane/4, k=lane%4) bijective
// ---------------------------------------------------------------------------
#define SB 136
#define SA 68
#define WS_WORDS (256 * SB)                    // 34816
#define SMEM_WORDS (WS_WORDS + 128 * SA)       // 43520
#define GEMM_SMEM_BYTES (SMEM_WORDS * 4)       // 174080

__device__ __forceinline__ uint32_t f2tf32(float v) {
    uint32_t r;
    asm("cvt.rna.tf32.f32 %0, %1;" : "=r"(r) : "f"(v));
    return r;
}

__global__ void __launch_bounds__(512, 1)
sage_gemm_mma(const float* __restrict__ x,
              const float* __restrict__ wl,
              const float* __restrict__ wr,
              const float* __restrict__ bias,
              float* __restrict__ out,
              int do_relu) {
    extern __shared__ float sm[];
    float* wS = sm;              // [256][SB]
    float* aS = sm + WS_WORDS;   // [128][SA]

    const int tid = threadIdx.x;
    const int wid = tid >> 5;
    const int lane = tid & 31;
    const int grp = lane >> 2;    // 0..7
    const int tig = lane & 3;     // 0..3
    const int warp_m = wid & 3;   // m offset = 32*warp_m
    const int warp_n = wid >> 2;  // n offset = 32*warp_n

    // ---- Stage B = W'^T once: wS[k][n] = tf32(k<128 ? wl[k][n] : wr[k-128][n])
    for (int i = tid; i < 256 * 128; i += 512) {
        int k = i >> 7, n = i & 127;
        float v = (k < 128) ? wl[k * 128 + n] : wr[(k - 128) * 128 + n];
        wS[k * SB + n] = __uint_as_float(f2tf32(v));
    }

    for (int t = blockIdx.x; t < NUM_TILES; t += gridDim.x) {
        const int m_base = t * M_TILE;
        float acc[32];
#pragma unroll
        for (int i = 0; i < 32; i++) acc[i] = 0.f;

        for (int chunk = 0; chunk < 4; chunk++) {
            __syncthreads();  // previous aS consumers done (also fences wS stage)
            // ---- Stage A chunk [128 m][64 k], tf32-converted ----
            for (int i = tid; i < 2048; i += 512) {
                int m = i >> 4;
                int kq = i & 15;
                int gm = m_base + m;
                int kg = chunk * 64 + (kq << 2);
                float4 v = make_float4(0.f, 0.f, 0.f, 0.f);
                if (gm < N_NODES) {
                    if (kg < 128) {
                        v = *(const float4*)(g_agg + (size_t)gm * D + kg);
                        float s = g_inv[gm];
                        v.x *= s; v.y *= s; v.z *= s; v.w *= s;
                    } else {
                        v = *(const float4*)(x + (size_t)gm * D + (kg - 128));
                    }
                }
                float4 c;
                c.x = __uint_as_float(f2tf32(v.x));
                c.y = __uint_as_float(f2tf32(v.y));
                c.z = __uint_as_float(f2tf32(v.z));
                c.w = __uint_as_float(f2tf32(v.w));
                *(float4*)&aS[m * SA + (kq << 2)] = c;
            }
            __syncthreads();

            // ---- Compute: 8 k-atoms of K=8 ----
#pragma unroll
            for (int ka = 0; ka < 8; ka++) {
                const int kc = ka * 8;
                const int kw = chunk * 64 + kc;
                uint32_t bfr[8];
#pragma unroll
                for (int j = 0; j < 4; j++) {
                    int nb = warp_n * 32 + j * 8 + grp;
                    bfr[j * 2]     = __float_as_uint(wS[(kw + tig) * SB + nb]);
                    bfr[j * 2 + 1] = __float_as_uint(wS[(kw + tig + 4) * SB + nb]);
                }
                uint32_t afr[8];
#pragma unroll
                for (int i = 0; i < 2; i++) {
                    int mb = warp_m * 32 + i * 16;
                    afr[i * 4 + 0] = __float_as_uint(aS[(mb + grp) * SA + kc + tig]);
                    afr[i * 4 + 1] = __float_as_uint(aS[(mb + grp + 8) * SA + kc + tig]);
                    afr[i * 4 + 2] = __float_as_uint(aS[(mb + grp) * SA + kc + tig + 4]);
                    afr[i * 4 + 3] = __float_as_uint(aS[(mb + grp + 8) * SA + kc + tig + 4]);
                }
#pragma unroll
                for (int i = 0; i < 2; i++)
#pragma unroll
                    for (int j = 0; j < 4; j++) {
                        float* c = &acc[(i * 4 + j) * 4];
                        asm volatile(
                            "mma.sync.aligned.m16n8k8.row.col.f32.tf32.tf32.f32 "
                            "{%0,%1,%2,%3}, {%4,%5,%6,%7}, {%8,%9}, {%0,%1,%2,%3};"
                            : "+f"(c[0]), "+f"(c[1]), "+f"(c[2]), "+f"(c[3])
                            : "r"(afr[i * 4]), "r"(afr[i * 4 + 1]),
                              "r"(afr[i * 4 + 2]), "r"(afr[i * 4 + 3]),
                              "r"(bfr[j * 2]), "r"(bfr[j * 2 + 1]));
                    }
            }
        }

        // ---- Epilogue: bias (+ReLU), store float2 per c-pair ----
#pragma unroll
        for (int j = 0; j < 4; j++) {
            int c0 = warp_n * 32 + j * 8 + 2 * tig;
            float b0 = bias[c0], b1 = bias[c0 + 1];
#pragma unroll
            for (int i = 0; i < 2; i++) {
                float* a = &acc[(i * 4 + j) * 4];
                int r0 = m_base + warp_m * 32 + i * 16 + grp;
#pragma unroll
                for (int h = 0; h < 2; h++) {
                    int r = r0 + h * 8;
                    if (r < N_NODES) {
                        float v0 = a[h * 2 + 0] + b0;
                        float v1 = a[h * 2 + 1] + b1;
                        if (do_relu) { v0 = fmaxf(v0, 0.f); v1 = fmaxf(v1, 0.f); }
                        *(float2*)(out + (size_t)r * D + c0) = make_float2(v0, v1);
                    }
                }
            }
        }
    }
}

// ---------------------------------------------------------------------------
// Launcher
// ---------------------------------------------------------------------------
extern "C" void kernel_launch(void* const* d_in, const int* in_sizes, int n_in,
                              void* d_out, int out_size) {
    const int* edge_index = (const int*)d_in[0];   // int32 (JAX default int)
    const float* node_emb = (const float*)d_in[1];
    const float* w1_l = (const float*)d_in[2];
    const float* b1_l = (const float*)d_in[3];
    const float* w1_r = (const float*)d_in[4];
    const float* w2_l = (const float*)d_in[5];
    const float* b2_l = (const float*)d_in[6];
    const float* w2_r = (const float*)d_in[7];
    float* out = (float*)d_out;

    static bool attr_set = false;
    if (!attr_set) {
        cudaFuncSetAttribute(sage_gemm_mma,
                             cudaFuncAttributeMaxDynamicSharedMemorySize,
                             GEMM_SMEM_BYTES);
        attr_set = true;
    }

    float* agg_p;  cudaGetSymbolAddress((void**)&agg_p, g_agg);
    float* cnt_p;  cudaGetSymbolAddress((void**)&cnt_p, g_cnt);
    float* h1_p;   cudaGetSymbolAddress((void**)&h1_p, g_h1);

    const int agg4 = N_NODES * D / 4;

    // zero counts + layer-1 accumulator
    zero_kernel<<<64, 256>>>((float4*)cnt_p, N_NODES / 4);
    zero_kernel<<<2048, 256>>>((float4*)agg_p, agg4);

    // --- layer 1 ---
    scatter_kernel<<<2048, 256>>>(edge_index, node_emb, 1);
    inv_kernel<<<(N_NODES + 255) / 256, 256>>>();
    sage_gemm_mma<<<148, 512, GEMM_SMEM_BYTES>>>(node_emb, w1_l, w1_r, b1_l,
                                                 h1_p, 1);

    // --- layer 2 ---
    zero_kernel<<<2048, 256>>>((float4*)agg_p, agg4);
    scatter_kernel<<<2048, 256>>>(edge_index, h1_p, 0);
    sage_gemm_mma<<<148, 512, GEMM_SMEM_BYTES>>>(h1_p, w2_l, w2_r, b2_l,
                                                 out, 0);

    (void)in_sizes; (void)n_in; (void)out_size;
}